// round 7
// baseline (speedup 1.0000x reference)
#include <cuda_runtime.h>
#include <cuda_bf16.h>
#include <cstdint>
#include <math.h>

// ---------------- problem constants ----------------
constexpr int CB = 2;        // batch
constexpr int CS = 2048;     // seq
constexpr int CD = 1024;     // model dim
constexpr int CH = 8;        // heads
constexpr int CHD = 128;     // head dim
constexpr int CM = CB * CS;  // 4096 rows

// ---------------- scratch (device globals; no allocations allowed) ----------
__device__ float g_Sf[CB * CS * CD];  // self_force = x @ Wself^T (fp32)

__device__ __nv_bfloat16 g_xh[CM * CD];
__device__ __nv_bfloat16 g_xl[CM * CD];
__device__ __nv_bfloat16 g_wh[4][CD * CD];
__device__ __nv_bfloat16 g_wl[4][CD * CD];

__device__ __nv_bfloat16 g_Kh[CB * CS * CD];
__device__ __nv_bfloat16 g_Kl[CB * CS * CD];
__device__ __nv_bfloat16 g_Vb[CB * CS * CD];

// ============================================================================
// PTX helpers (family-common sm_80+ only; tcgen05 unavailable on this ptxas)
// ============================================================================
__device__ __forceinline__ uint32_t smem_u32(const void* p) {
    uint32_t a;
    asm("{ .reg .u64 t; cvta.to.shared.u64 t, %1; cvt.u32.u64 %0, t; }" : "=r"(a) : "l"(p));
    return a;
}
__device__ __forceinline__ void cp16(uint32_t dst, const void* src) {
    asm volatile("cp.async.cg.shared.global [%0], [%1], 16;" :: "r"(dst), "l"(src) : "memory");
}
#define CP_COMMIT() asm volatile("cp.async.commit_group;" ::: "memory")

__device__ __forceinline__ void ldsm4(uint32_t* r, uint32_t addr) {
    asm volatile("ldmatrix.sync.aligned.m8n8.x4.shared.b16 {%0,%1,%2,%3}, [%4];"
                 : "=r"(r[0]), "=r"(r[1]), "=r"(r[2]), "=r"(r[3]) : "r"(addr));
}
__device__ __forceinline__ void ldsm4t(uint32_t* r, uint32_t addr) {
    asm volatile("ldmatrix.sync.aligned.m8n8.x4.trans.shared.b16 {%0,%1,%2,%3}, [%4];"
                 : "=r"(r[0]), "=r"(r[1]), "=r"(r[2]), "=r"(r[3]) : "r"(addr));
}
__device__ __forceinline__ void mma16816(float* d, const uint32_t* a, const uint32_t* b) {
    asm volatile(
        "mma.sync.aligned.m16n8k16.row.col.f32.bf16.bf16.f32 "
        "{%0,%1,%2,%3}, {%4,%5,%6,%7}, {%8,%9}, {%0,%1,%2,%3};\n"
        : "+f"(d[0]), "+f"(d[1]), "+f"(d[2]), "+f"(d[3])
        : "r"(a[0]), "r"(a[1]), "r"(a[2]), "r"(a[3]), "r"(b[0]), "r"(b[1]));
}

// ---- fp32 -> bf16 hi/lo helpers --------------------------------------------
__device__ __forceinline__ void split4(float4 v, __nv_bfloat162* hi2, __nv_bfloat162* lo2,
                                       size_t i2) {
    __nv_bfloat16 h0 = __float2bfloat16_rn(v.x), h1 = __float2bfloat16_rn(v.y);
    __nv_bfloat16 h2 = __float2bfloat16_rn(v.z), h3 = __float2bfloat16_rn(v.w);
    __nv_bfloat16 l0 = __float2bfloat16_rn(v.x - __bfloat162float(h0));
    __nv_bfloat16 l1 = __float2bfloat16_rn(v.y - __bfloat162float(h1));
    __nv_bfloat16 l2 = __float2bfloat16_rn(v.z - __bfloat162float(h2));
    __nv_bfloat16 l3 = __float2bfloat16_rn(v.w - __bfloat162float(h3));
    hi2[i2]     = __nv_bfloat162(h0, h1);
    hi2[i2 + 1] = __nv_bfloat162(h2, h3);
    lo2[i2]     = __nv_bfloat162(l0, l1);
    lo2[i2 + 1] = __nv_bfloat162(l2, l3);
}
__device__ __forceinline__ void store_split2(__nv_bfloat16* H, __nv_bfloat16* L,
                                             size_t off, float a, float b) {
    __nv_bfloat16 h0 = __float2bfloat16_rn(a), h1 = __float2bfloat16_rn(b);
    __nv_bfloat16 l0 = __float2bfloat16_rn(a - __bfloat162float(h0));
    __nv_bfloat16 l1 = __float2bfloat16_rn(b - __bfloat162float(h1));
    *(__nv_bfloat162*)(H + off) = __nv_bfloat162(h0, h1);
    *(__nv_bfloat162*)(L + off) = __nv_bfloat162(l0, l1);
}

// ============================================================================
// prep: one kernel splitting x and all 4 weights into bf16 hi/lo
// ============================================================================
constexpr size_t XQ = (size_t)CM * CD / 4;
constexpr size_t WQ = (size_t)CD * CD / 4;
__global__ __launch_bounds__(256) void prep(const float* __restrict__ x,
                                            const float* __restrict__ Wk,
                                            const float* __restrict__ Wv,
                                            const float* __restrict__ Ws,
                                            const float* __restrict__ Wo) {
    size_t i = (size_t)blockIdx.x * 256 + threadIdx.x;
    if (i < XQ) {
        split4(((const float4*)x)[i], (__nv_bfloat162*)g_xh, (__nv_bfloat162*)g_xl, i * 2);
    } else {
        size_t j = i - XQ;
        int w = (int)(j / WQ);
        size_t o = j % WQ;
        const float* W = (w == 0) ? Wk : (w == 1) ? Wv : (w == 2) ? Ws : Wo;
        split4(((const float4*)W)[o], (__nv_bfloat162*)g_wh[w], (__nv_bfloat162*)g_wl[w], o * 2);
    }
}

// ============================================================================
// HMMA bf16-split GEMM core:  C = A @ W^T, 128x128 CTA tile.
// MMA order is term-major (hh x4, hl x4, lh x4): same-acc reuse distance 4
// so HMMA RAW latency is hidden at reciprocal-throughput issue.
// ============================================================================
constexpr int RSTRIDE = 80;
constexpr int TILE_B = 128 * RSTRIDE;
constexpr int STAGE_B = 4 * TILE_B;
constexpr int G_SMEM = 2 * STAGE_B;

#define GEMM_CORE(Ah_, Al_, Bh_, Bl_)                                              \
    float acc[4][4][4];                                                            \
    _Pragma("unroll") for (int i = 0; i < 4; i++)                                  \
        _Pragma("unroll") for (int j = 0; j < 4; j++)                              \
            _Pragma("unroll") for (int r = 0; r < 4; r++) acc[i][j][r] = 0.f;      \
    const int lrow0 = tid >> 2, lc0 = tid & 3;                                     \
    const int lrow1 = (tid + 256) >> 2, lc1 = tid & 3;                             \
    {                                                                              \
        uint32_t st_ = sb;                                                         \
        size_t gA0 = (size_t)(m0 + lrow0) * CD + lc0 * 8;                          \
        size_t gA1 = (size_t)(m0 + lrow1) * CD + lc1 * 8;                          \
        size_t gB0 = (size_t)(n0 + lrow0) * CD + lc0 * 8;                          \
        size_t gB1 = (size_t)(n0 + lrow1) * CD + lc1 * 8;                          \
        uint32_t s0 = lrow0 * RSTRIDE + lc0 * 16, s1 = lrow1 * RSTRIDE + lc1 * 16; \
        cp16(st_ + 0 * TILE_B + s0, Ah_ + gA0);                                    \
        cp16(st_ + 0 * TILE_B + s1, Ah_ + gA1);                                    \
        cp16(st_ + 1 * TILE_B + s0, Al_ + gA0);                                    \
        cp16(st_ + 1 * TILE_B + s1, Al_ + gA1);                                    \
        cp16(st_ + 2 * TILE_B + s0, Bh_ + gB0);                                    \
        cp16(st_ + 2 * TILE_B + s1, Bh_ + gB1);                                    \
        cp16(st_ + 3 * TILE_B + s0, Bl_ + gB0);                                    \
        cp16(st_ + 3 * TILE_B + s1, Bl_ + gB1);                                    \
        CP_COMMIT();                                                               \
    }                                                                              \
    constexpr int NC = CD / 32;                                                    \
    for (int c = 0; c < NC; c++) {                                                 \
        if (c + 1 < NC) {                                                          \
            int k0 = (c + 1) * 32;                                                 \
            uint32_t st_ = sb + ((c + 1) & 1) * STAGE_B;                           \
            size_t gA0 = (size_t)(m0 + lrow0) * CD + k0 + lc0 * 8;                 \
            size_t gA1 = (size_t)(m0 + lrow1) * CD + k0 + lc1 * 8;                 \
            size_t gB0 = (size_t)(n0 + lrow0) * CD + k0 + lc0 * 8;                 \
            size_t gB1 = (size_t)(n0 + lrow1) * CD + k0 + lc1 * 8;                 \
            uint32_t s0 = lrow0 * RSTRIDE + lc0 * 16;                              \
            uint32_t s1 = lrow1 * RSTRIDE + lc1 * 16;                              \
            cp16(st_ + 0 * TILE_B + s0, Ah_ + gA0);                                \
            cp16(st_ + 0 * TILE_B + s1, Ah_ + gA1);                                \
            cp16(st_ + 1 * TILE_B + s0, Al_ + gA0);                                \
            cp16(st_ + 1 * TILE_B + s1, Al_ + gA1);                                \
            cp16(st_ + 2 * TILE_B + s0, Bh_ + gB0);                                \
            cp16(st_ + 2 * TILE_B + s1, Bh_ + gB1);                                \
            cp16(st_ + 3 * TILE_B + s0, Bl_ + gB0);                                \
            cp16(st_ + 3 * TILE_B + s1, Bl_ + gB1);                                \
            CP_COMMIT();                                                           \
            asm volatile("cp.async.wait_group 1;" ::: "memory");                   \
        } else {                                                                   \
            asm volatile("cp.async.wait_group 0;" ::: "memory");                   \
        }                                                                          \
        __syncthreads();                                                           \
        const uint32_t st = sb + (c & 1) * STAGE_B;                                \
        _Pragma("unroll") for (int h = 0; h < 2; h++) {                            \
            uint32_t bh[8], bl[8];                                                 \
            _Pragma("unroll") for (int j2 = 0; j2 < 2; j2++) {                     \
                uint32_t off = (uint32_t)((wn + j2 * 16 + (lane & 15)) * RSTRIDE + \
                                          (h * 2 + (lane >> 4)) * 16);             \
                ldsm4(bh + j2 * 4, st + 2 * TILE_B + off);                         \
                ldsm4(bl + j2 * 4, st + 3 * TILE_B + off);                         \
            }                                                                      \
            _Pragma("unroll") for (int i = 0; i < 4; i++) {                        \
                uint32_t aoff = (uint32_t)((wm + i * 16 + (lane & 15)) * RSTRIDE + \
                                           (h * 2 + (lane >> 4)) * 16);            \
                uint32_t ah[4], al[4];                                             \
                ldsm4(ah, st + 0 * TILE_B + aoff);                                 \
                ldsm4(al, st + 1 * TILE_B + aoff);                                 \
                /* term-major: 4 independent mmas per pass */                      \
                _Pragma("unroll") for (int j = 0; j < 4; j++) {                    \
                    uint32_t b2[2] = {bh[(j >> 1) * 4 + (j & 1)],                  \
                                      bh[(j >> 1) * 4 + 2 + (j & 1)]};             \
                    mma16816(acc[i][j], ah, b2);                                   \
                }                                                                  \
                _Pragma("unroll") for (int j = 0; j < 4; j++) {                    \
                    uint32_t b2[2] = {bl[(j >> 1) * 4 + (j & 1)],                  \
                                      bl[(j >> 1) * 4 + 2 + (j & 1)]};             \
                    mma16816(acc[i][j], ah, b2);                                   \
                }                                                                  \
                _Pragma("unroll") for (int j = 0; j < 4; j++) {                    \
                    uint32_t b2[2] = {bh[(j >> 1) * 4 + (j & 1)],                  \
                                      bh[(j >> 1) * 4 + 2 + (j & 1)]};             \
                    mma16816(acc[i][j], al, b2);                                   \
                }                                                                  \
            }                                                                      \
        }                                                                          \
        __syncthreads();                                                           \
    }

// ---- the 3 projection GEMMs in one launch ----------------------------------
__global__ __launch_bounds__(256, 2) void gemm3() {
    extern __shared__ __align__(128) char smem[];
    const uint32_t sb = smem_u32(smem);
    const int tid = threadIdx.x, wid = tid >> 5, lane = tid & 31;
    const int mode = (int)(blockIdx.x >> 3);          // 0=K 1=V 2=Sf
    const int n0 = (int)(blockIdx.x & 7) * 128;
    const int m0 = (int)blockIdx.y * 128;
    const int wm = (wid >> 2) * 64;
    const int wn = (wid & 3) * 32;

    const __nv_bfloat16* Bh = g_wh[mode];
    const __nv_bfloat16* Bl = g_wl[mode];

    GEMM_CORE(g_xh, g_xl, Bh, Bl)

#pragma unroll
    for (int i = 0; i < 4; i++) {
        const int m = m0 + wm + i * 16 + (lane >> 2);
#pragma unroll
        for (int j = 0; j < 4; j++) {
            const int n = n0 + wn + j * 8 + (lane & 3) * 2;
            const size_t o0 = (size_t)m * CD + n;
            const size_t o1 = (size_t)(m + 8) * CD + n;
            if (mode == 2) {
                *(float2*)(g_Sf + o0) = make_float2(acc[i][j][0], acc[i][j][1]);
                *(float2*)(g_Sf + o1) = make_float2(acc[i][j][2], acc[i][j][3]);
            } else if (mode == 0) {
                store_split2(g_Kh, g_Kl, o0, acc[i][j][0], acc[i][j][1]);
                store_split2(g_Kh, g_Kl, o1, acc[i][j][2], acc[i][j][3]);
            } else {
                *(__nv_bfloat162*)(g_Vb + o0) =
                    __floats2bfloat162_rn(acc[i][j][0], acc[i][j][1]);
                *(__nv_bfloat162*)(g_Vb + o1) =
                    __floats2bfloat162_rn(acc[i][j][2], acc[i][j][3]);
            }
        }
    }
}

// ---- final GEMM: (P+Sf) @ Wout^T -> out ------------------------------------
__global__ __launch_bounds__(256, 2) void gemm_out(float* __restrict__ Cout) {
    extern __shared__ __align__(128) char smem[];
    const uint32_t sb = smem_u32(smem);
    const int tid = threadIdx.x, wid = tid >> 5, lane = tid & 31;
    const int n0 = (int)blockIdx.x * 128;
    const int m0 = (int)blockIdx.y * 128;
    const int wm = (wid >> 2) * 64;
    const int wn = (wid & 3) * 32;

    const __nv_bfloat16* Bh = g_wh[3];
    const __nv_bfloat16* Bl = g_wl[3];

    GEMM_CORE(g_xh, g_xl, Bh, Bl)

#pragma unroll
    for (int i = 0; i < 4; i++) {
        const int m = m0 + wm + i * 16 + (lane >> 2);
#pragma unroll
        for (int j = 0; j < 4; j++) {
            const int n = n0 + wn + j * 8 + (lane & 3) * 2;
            *(float2*)(Cout + (size_t)m * CD + n) = make_float2(acc[i][j][0], acc[i][j][1]);
            *(float2*)(Cout + (size_t)(m + 8) * CD + n) = make_float2(acc[i][j][2], acc[i][j][3]);
        }
    }
}

// ============================================================================
// FA2-style causal attention on HMMA (Q == K). Score mma loop term-major
// (reuse distance 8). Epilogue fused: (P+Sf) split -> g_xh/g_xl.
// ============================================================================
constexpr int A_RS = 272;
constexpr int A_TILE = 64 * A_RS;
constexpr int A_SMEM = 5 * A_TILE;

__global__ __launch_bounds__(128, 2) void fattn() {
    extern __shared__ __align__(128) char smem[];
    const uint32_t sb = smem_u32(smem);
    const uint32_t SQH = 0, SQL = A_TILE, SKH = 2 * A_TILE, SKL = 3 * A_TILE, SVB = 4 * A_TILE;

    const int qb = (int)(gridDim.x - 1 - blockIdx.x);  // heaviest first
    const int bh = blockIdx.y;
    const int b = bh >> 3, h = bh & 7;
    const int q0 = qb * 64;

    const int tid = threadIdx.x, wid = tid >> 5, lane = tid & 31;

    const __nv_bfloat16* Khg = g_Kh + (size_t)b * CS * CD + h * CHD;
    const __nv_bfloat16* Klg = g_Kl + (size_t)b * CS * CD + h * CHD;
    const __nv_bfloat16* Vbg = g_Vb + (size_t)b * CS * CD + h * CHD;

    for (int t = tid; t < 64 * 16; t += 128) {
        int row = t >> 4, g = t & 15;
        uint32_t so = (uint32_t)(row * A_RS + g * 16);
        cp16(sb + SQH + so, Khg + (size_t)(q0 + row) * CD + g * 8);
        cp16(sb + SQL + so, Klg + (size_t)(q0 + row) * CD + g * 8);
    }
    CP_COMMIT();

    float o[16][4];
#pragma unroll
    for (int t = 0; t < 16; t++)
#pragma unroll
        for (int r = 0; r < 4; r++) o[t][r] = 0.f;
    float m0r = -1e30f, m1r = -1e30f, l0 = 0.f, l1 = 0.f;
    const float scale = 0.08838834764831845f;  // 1/sqrt(128)

    for (int kb = 0; kb <= qb; kb++) {
        const int k0 = kb * 64;
        __syncthreads();
        for (int t = tid; t < 64 * 16; t += 128) {
            int row = t >> 4, g = t & 15;
            uint32_t so = (uint32_t)(row * A_RS + g * 16);
            cp16(sb + SKH + so, Khg + (size_t)(k0 + row) * CD + g * 8);
            cp16(sb + SKL + so, Klg + (size_t)(k0 + row) * CD + g * 8);
            cp16(sb + SVB + so, Vbg + (size_t)(k0 + row) * CD + g * 8);
        }
        CP_COMMIT();
        asm volatile("cp.async.wait_group 0;" ::: "memory");
        __syncthreads();

        float s[8][4];
#pragma unroll
        for (int j = 0; j < 8; j++)
#pragma unroll
            for (int r = 0; r < 4; r++) s[j][r] = 0.f;

#pragma unroll
        for (int ks = 0; ks < 8; ks++) {
            uint32_t qoff = (uint32_t)((wid * 16 + (lane & 15)) * A_RS + ks * 32 +
                                       (lane >> 4) * 16);
            uint32_t qh[4], ql[4];
            ldsm4(qh, sb + SQH + qoff);
            ldsm4(ql, sb + SQL + qoff);
            uint32_t khf[16], klf[16];
#pragma unroll
            for (int j4 = 0; j4 < 4; j4++) {
                uint32_t koff = (uint32_t)((j4 * 16 + (lane & 15)) * A_RS + ks * 32 +
                                           (lane >> 4) * 16);
                ldsm4(khf + j4 * 4, sb + SKH + koff);
                ldsm4(klf + j4 * 4, sb + SKL + koff);
            }
            // term-major: 8 independent mmas per pass
#pragma unroll
            for (int j = 0; j < 8; j++) {
                uint32_t b2[2] = {khf[(j >> 1) * 4 + (j & 1)], khf[(j >> 1) * 4 + 2 + (j & 1)]};
                mma16816(s[j], qh, b2);
            }
#pragma unroll
            for (int j = 0; j < 8; j++) {
                uint32_t b2[2] = {klf[(j >> 1) * 4 + (j & 1)], klf[(j >> 1) * 4 + 2 + (j & 1)]};
                mma16816(s[j], qh, b2);
            }
#pragma unroll
            for (int j = 0; j < 8; j++) {
                uint32_t b2[2] = {khf[(j >> 1) * 4 + (j & 1)], khf[(j >> 1) * 4 + 2 + (j & 1)]};
                mma16816(s[j], ql, b2);
            }
        }

        const int r0l = wid * 16 + (lane >> 2);
#pragma unroll
        for (int j = 0; j < 8; j++) {
#pragma unroll
            for (int r = 0; r < 4; r++) s[j][r] = -s[j][r] * scale;
            if (kb == qb) {
                int cl = j * 8 + (lane & 3) * 2;
                if (cl > r0l) s[j][0] = -1e30f;
                if (cl + 1 > r0l) s[j][1] = -1e30f;
                if (cl > r0l + 8) s[j][2] = -1e30f;
                if (cl + 1 > r0l + 8) s[j][3] = -1e30f;
            }
        }

        float mx0 = -1e30f, mx1 = -1e30f;
#pragma unroll
        for (int j = 0; j < 8; j++) {
            mx0 = fmaxf(mx0, fmaxf(s[j][0], s[j][1]));
            mx1 = fmaxf(mx1, fmaxf(s[j][2], s[j][3]));
        }
        mx0 = fmaxf(mx0, __shfl_xor_sync(0xffffffffu, mx0, 1));
        mx0 = fmaxf(mx0, __shfl_xor_sync(0xffffffffu, mx0, 2));
        mx1 = fmaxf(mx1, __shfl_xor_sync(0xffffffffu, mx1, 1));
        mx1 = fmaxf(mx1, __shfl_xor_sync(0xffffffffu, mx1, 2));
        const float mn0 = fmaxf(m0r, mx0), mn1 = fmaxf(m1r, mx1);
        const float a0 = __expf(m0r - mn0), a1 = __expf(m1r - mn1);
        float sum0 = 0.f, sum1 = 0.f;
#pragma unroll
        for (int j = 0; j < 8; j++) {
            s[j][0] = __expf(s[j][0] - mn0);
            s[j][1] = __expf(s[j][1] - mn0);
            s[j][2] = __expf(s[j][2] - mn1);
            s[j][3] = __expf(s[j][3] - mn1);
            sum0 += s[j][0] + s[j][1];
            sum1 += s[j][2] + s[j][3];
        }
        sum0 += __shfl_xor_sync(0xffffffffu, sum0, 1);
        sum0 += __shfl_xor_sync(0xffffffffu, sum0, 2);
        sum1 += __shfl_xor_sync(0xffffffffu, sum1, 1);
        sum1 += __shfl_xor_sync(0xffffffffu, sum1, 2);
        l0 = l0 * a0 + sum0;
        l1 = l1 * a1 + sum1;
        m0r = mn0; m1r = mn1;
#pragma unroll
        for (int t = 0; t < 16; t++) {
            o[t][0] *= a0; o[t][1] *= a0; o[t][2] *= a1; o[t][3] *= a1;
        }

#pragma unroll
        for (int kg = 0; kg < 4; kg++) {
            uint32_t pa[4];
            {
                __nv_bfloat162 t0 = __floats2bfloat162_rn(s[2 * kg][0], s[2 * kg][1]);
                __nv_bfloat162 t1 = __floats2bfloat162_rn(s[2 * kg][2], s[2 * kg][3]);
                __nv_bfloat162 t2 = __floats2bfloat162_rn(s[2 * kg + 1][0], s[2 * kg + 1][1]);
                __nv_bfloat162 t3 = __floats2bfloat162_rn(s[2 * kg + 1][2], s[2 * kg + 1][3]);
                pa[0] = *(uint32_t*)&t0; pa[1] = *(uint32_t*)&t1;
                pa[2] = *(uint32_t*)&t2; pa[3] = *(uint32_t*)&t3;
            }
#pragma unroll
            for (int n2 = 0; n2 < 8; n2++) {
                uint32_t voff = (uint32_t)((kg * 16 + (lane & 15)) * A_RS + n2 * 32 +
                                           (lane >> 4) * 16);
                uint32_t vf[4];
                ldsm4t(vf, sb + SVB + voff);
                uint32_t b0[2] = {vf[0], vf[1]};
                uint32_t b1[2] = {vf[2], vf[3]};
                mma16816(o[2 * n2], pa, b0);
                mma16816(o[2 * n2 + 1], pa, b1);
            }
        }
    }

    // ---- fused epilogue: (P_norm + Sf) -> split -> g_xh/g_xl ----------------
    const float inv0 = 1.f / l0, inv1 = 1.f / l1;
    const size_t row0 = (size_t)(b * CS + q0 + wid * 16 + (lane >> 2));
#pragma unroll
    for (int t = 0; t < 16; t++) {
        const int col = h * CHD + t * 8 + (lane & 3) * 2;
        const size_t o0 = row0 * CD + col;
        const size_t o1 = (row0 + 8) * CD + col;
        float2 sf0 = *(const float2*)(g_Sf + o0);
        float2 sf1 = *(const float2*)(g_Sf + o1);
        store_split2(g_xh, g_xl, o0, o[t][0] * inv0 + sf0.x, o[t][1] * inv0 + sf0.y);
        store_split2(g_xh, g_xl, o1, o[t][2] * inv1 + sf1.x, o[t][3] * inv1 + sf1.y);
    }
}

// ============================================================================
// launch
// ============================================================================
extern "C" void kernel_launch(void* const* d_in, const int* in_sizes, int n_in,
                              void* d_out, int out_size) {
    const float* x  = (const float*)d_in[0];
    const float* Wk = (const float*)d_in[1];
    const float* Wv = (const float*)d_in[2];
    const float* Ws = (const float*)d_in[3];
    const float* Wo = (const float*)d_in[4];
    float* out = (float*)d_out;

    cudaFuncSetAttribute(gemm3, cudaFuncAttributeMaxDynamicSharedMemorySize, G_SMEM);
    cudaFuncSetAttribute(gemm_out, cudaFuncAttributeMaxDynamicSharedMemorySize, G_SMEM);
    cudaFuncSetAttribute(fattn, cudaFuncAttributeMaxDynamicSharedMemorySize, A_SMEM);

    const int PB = (int)((XQ + 4 * WQ) / 256);
    prep<<<PB, 256>>>(x, Wk, Wv, Ws, Wo);

    gemm3<<<dim3(24, CM / 128), 256, G_SMEM>>>();     // -> g_Kh/g_Kl, g_Vb, g_Sf

    fattn<<<dim3(CS / 64, CB * CH), 128, A_SMEM>>>(); // -> g_xh/g_xl (=P+Sf split)

    gemm_out<<<dim3(CD / 128, CM / 128), 256, G_SMEM>>>(out);
}

// round 8
// speedup vs baseline: 1.1044x; 1.1044x over previous
#include <cuda_runtime.h>
#include <cuda_bf16.h>
#include <cstdint>
#include <math.h>

// ---------------- problem constants ----------------
constexpr int CB = 2;        // batch
constexpr int CS = 2048;     // seq
constexpr int CD = 1024;     // model dim
constexpr int CH = 8;        // heads
constexpr int CHD = 128;     // head dim
constexpr int CM = CB * CS;  // 4096 rows

// ---------------- scratch (device globals; no allocations allowed) ----------
__device__ float g_Sf[CB * CS * CD];  // self_force = x @ Wself^T (fp32)

__device__ __nv_bfloat16 g_xh[CM * CD];
__device__ __nv_bfloat16 g_xl[CM * CD];
__device__ __nv_bfloat16 g_wh[4][CD * CD];
__device__ __nv_bfloat16 g_wl[4][CD * CD];

__device__ __nv_bfloat16 g_Kh[CB * CS * CD];
__device__ __nv_bfloat16 g_Kl[CB * CS * CD];
__device__ __nv_bfloat16 g_Vb[CB * CS * CD];

// ============================================================================
// PTX helpers (family-common sm_80+ only; tcgen05 unavailable on this ptxas)
// ============================================================================
__device__ __forceinline__ uint32_t smem_u32(const void* p) {
    uint32_t a;
    asm("{ .reg .u64 t; cvta.to.shared.u64 t, %1; cvt.u32.u64 %0, t; }" : "=r"(a) : "l"(p));
    return a;
}
__device__ __forceinline__ void cp16(uint32_t dst, const void* src) {
    asm volatile("cp.async.cg.shared.global [%0], [%1], 16;" :: "r"(dst), "l"(src) : "memory");
}
#define CP_COMMIT() asm volatile("cp.async.commit_group;" ::: "memory")
#define CP_WAIT0()  asm volatile("cp.async.wait_group 0;" ::: "memory")

__device__ __forceinline__ void ldsm4(uint32_t* r, uint32_t addr) {
    asm volatile("ldmatrix.sync.aligned.m8n8.x4.shared.b16 {%0,%1,%2,%3}, [%4];"
                 : "=r"(r[0]), "=r"(r[1]), "=r"(r[2]), "=r"(r[3]) : "r"(addr));
}
__device__ __forceinline__ void ldsm4t(uint32_t* r, uint32_t addr) {
    asm volatile("ldmatrix.sync.aligned.m8n8.x4.trans.shared.b16 {%0,%1,%2,%3}, [%4];"
                 : "=r"(r[0]), "=r"(r[1]), "=r"(r[2]), "=r"(r[3]) : "r"(addr));
}
__device__ __forceinline__ void mma16816(float* d, const uint32_t* a, const uint32_t* b) {
    asm volatile(
        "mma.sync.aligned.m16n8k16.row.col.f32.bf16.bf16.f32 "
        "{%0,%1,%2,%3}, {%4,%5,%6,%7}, {%8,%9}, {%0,%1,%2,%3};\n"
        : "+f"(d[0]), "+f"(d[1]), "+f"(d[2]), "+f"(d[3])
        : "r"(a[0]), "r"(a[1]), "r"(a[2]), "r"(a[3]), "r"(b[0]), "r"(b[1]));
}

// ---- fp32 -> bf16 hi/lo helpers --------------------------------------------
__device__ __forceinline__ void split4(float4 v, __nv_bfloat162* hi2, __nv_bfloat162* lo2,
                                       size_t i2) {
    __nv_bfloat16 h0 = __float2bfloat16_rn(v.x), h1 = __float2bfloat16_rn(v.y);
    __nv_bfloat16 h2 = __float2bfloat16_rn(v.z), h3 = __float2bfloat16_rn(v.w);
    __nv_bfloat16 l0 = __float2bfloat16_rn(v.x - __bfloat162float(h0));
    __nv_bfloat16 l1 = __float2bfloat16_rn(v.y - __bfloat162float(h1));
    __nv_bfloat16 l2 = __float2bfloat16_rn(v.z - __bfloat162float(h2));
    __nv_bfloat16 l3 = __float2bfloat16_rn(v.w - __bfloat162float(h3));
    hi2[i2]     = __nv_bfloat162(h0, h1);
    hi2[i2 + 1] = __nv_bfloat162(h2, h3);
    lo2[i2]     = __nv_bfloat162(l0, l1);
    lo2[i2 + 1] = __nv_bfloat162(l2, l3);
}
__device__ __forceinline__ void store_split2(__nv_bfloat16* H, __nv_bfloat16* L,
                                             size_t off, float a, float b) {
    __nv_bfloat16 h0 = __float2bfloat16_rn(a), h1 = __float2bfloat16_rn(b);
    __nv_bfloat16 l0 = __float2bfloat16_rn(a - __bfloat162float(h0));
    __nv_bfloat16 l1 = __float2bfloat16_rn(b - __bfloat162float(h1));
    *(__nv_bfloat162*)(H + off) = __nv_bfloat162(h0, h1);
    *(__nv_bfloat162*)(L + off) = __nv_bfloat162(l0, l1);
}

// ============================================================================
// prep: one kernel splitting x and all 4 weights into bf16 hi/lo
// ============================================================================
constexpr size_t XQ = (size_t)CM * CD / 4;
constexpr size_t WQ = (size_t)CD * CD / 4;
__global__ __launch_bounds__(256) void prep(const float* __restrict__ x,
                                            const float* __restrict__ Wk,
                                            const float* __restrict__ Wv,
                                            const float* __restrict__ Ws,
                                            const float* __restrict__ Wo) {
    size_t i = (size_t)blockIdx.x * 256 + threadIdx.x;
    if (i < XQ) {
        split4(((const float4*)x)[i], (__nv_bfloat162*)g_xh, (__nv_bfloat162*)g_xl, i * 2);
    } else {
        size_t j = i - XQ;
        int w = (int)(j / WQ);
        size_t o = j % WQ;
        const float* W = (w == 0) ? Wk : (w == 1) ? Wv : (w == 2) ? Ws : Wo;
        split4(((const float4*)W)[o], (__nv_bfloat162*)g_wh[w], (__nv_bfloat162*)g_wl[w], o * 2);
    }
}

// ============================================================================
// HMMA bf16-split GEMM core:  C = A @ W^T, 128x128 CTA tile, 8 warps (64x32).
// F3=true : 3-term split (Ah*Bh + Ah*Bl + Al*Bh).  F3=false : plain bf16.
// Single __syncthreads per K-chunk: wait -> sync -> prefetch(c+1) -> compute(c).
// The top sync proves all warps finished compute(c-1), so prefetch into that
// buffer is race-free without a trailing barrier.
// ============================================================================
constexpr int RSTRIDE = 80;
constexpr int TILE_B = 128 * RSTRIDE;
constexpr int STAGE_B = 4 * TILE_B;
constexpr int G_SMEM = 2 * STAGE_B;

template <bool F3>
__device__ __forceinline__ void g_load(uint32_t st_, int m0, int n0, int k0,
                                       int lrow0, int lrow1, int lc,
                                       const __nv_bfloat16* Ah_, const __nv_bfloat16* Al_,
                                       const __nv_bfloat16* Bh_, const __nv_bfloat16* Bl_) {
    size_t gA0 = (size_t)(m0 + lrow0) * CD + k0 + lc * 8;
    size_t gA1 = (size_t)(m0 + lrow1) * CD + k0 + lc * 8;
    size_t gB0 = (size_t)(n0 + lrow0) * CD + k0 + lc * 8;
    size_t gB1 = (size_t)(n0 + lrow1) * CD + k0 + lc * 8;
    uint32_t s0 = lrow0 * RSTRIDE + lc * 16, s1 = lrow1 * RSTRIDE + lc * 16;
    cp16(st_ + 0 * TILE_B + s0, Ah_ + gA0);
    cp16(st_ + 0 * TILE_B + s1, Ah_ + gA1);
    cp16(st_ + 2 * TILE_B + s0, Bh_ + gB0);
    cp16(st_ + 2 * TILE_B + s1, Bh_ + gB1);
    if (F3) {
        cp16(st_ + 1 * TILE_B + s0, Al_ + gA0);
        cp16(st_ + 1 * TILE_B + s1, Al_ + gA1);
        cp16(st_ + 3 * TILE_B + s0, Bl_ + gB0);
        cp16(st_ + 3 * TILE_B + s1, Bl_ + gB1);
    }
    CP_COMMIT();
}

template <bool F3>
__device__ __forceinline__ void gemm_core(uint32_t sb, int tid, int lane, int wm, int wn,
                                          int m0, int n0,
                                          const __nv_bfloat16* Ah_, const __nv_bfloat16* Al_,
                                          const __nv_bfloat16* Bh_, const __nv_bfloat16* Bl_,
                                          float acc[4][4][4]) {
#pragma unroll
    for (int i = 0; i < 4; i++)
#pragma unroll
        for (int j = 0; j < 4; j++)
#pragma unroll
            for (int r = 0; r < 4; r++) acc[i][j][r] = 0.f;

    const int lrow0 = tid >> 2, lc = tid & 3;
    const int lrow1 = lrow0 + 64;

    g_load<F3>(sb, m0, n0, 0, lrow0, lrow1, lc, Ah_, Al_, Bh_, Bl_);

    constexpr int NC = CD / 32;
    for (int c = 0; c < NC; c++) {
        CP_WAIT0();
        __syncthreads();
        if (c + 1 < NC)
            g_load<F3>(sb + ((c + 1) & 1) * STAGE_B, m0, n0, (c + 1) * 32,
                       lrow0, lrow1, lc, Ah_, Al_, Bh_, Bl_);

        const uint32_t st = sb + (c & 1) * STAGE_B;
#pragma unroll
        for (int h = 0; h < 2; h++) {
            uint32_t bh[8], bl[8];
#pragma unroll
            for (int j2 = 0; j2 < 2; j2++) {
                uint32_t off = (uint32_t)((wn + j2 * 16 + (lane & 15)) * RSTRIDE +
                                          (h * 2 + (lane >> 4)) * 16);
                ldsm4(bh + j2 * 4, st + 2 * TILE_B + off);
                if (F3) ldsm4(bl + j2 * 4, st + 3 * TILE_B + off);
            }
#pragma unroll
            for (int i = 0; i < 4; i++) {
                uint32_t aoff = (uint32_t)((wm + i * 16 + (lane & 15)) * RSTRIDE +
                                           (h * 2 + (lane >> 4)) * 16);
                uint32_t ah[4], al[4];
                ldsm4(ah, st + 0 * TILE_B + aoff);
                if (F3) ldsm4(al, st + 1 * TILE_B + aoff);
#pragma unroll
                for (int j = 0; j < 4; j++) {
                    uint32_t b2[2] = {bh[(j >> 1) * 4 + (j & 1)], bh[(j >> 1) * 4 + 2 + (j & 1)]};
                    mma16816(acc[i][j], ah, b2);
                }
                if (F3) {
#pragma unroll
                    for (int j = 0; j < 4; j++) {
                        uint32_t b2[2] = {bl[(j >> 1) * 4 + (j & 1)],
                                          bl[(j >> 1) * 4 + 2 + (j & 1)]};
                        mma16816(acc[i][j], ah, b2);
                    }
#pragma unroll
                    for (int j = 0; j < 4; j++) {
                        uint32_t b2[2] = {bh[(j >> 1) * 4 + (j & 1)],
                                          bh[(j >> 1) * 4 + 2 + (j & 1)]};
                        mma16816(acc[i][j], al, b2);
                    }
                }
            }
        }
        __syncthreads();  // all warps done with buffer (c&1) before it is reloaded
    }
}

// ---- the 3 projection GEMMs in one launch ----------------------------------
// mode 0 (K): 3-term, epilogue splits to g_Kh/g_Kl
// mode 1 (V): 1-term plain bf16 (feeds bf16 P@V anyway), epilogue -> g_Vb
// mode 2 (Sf): 3-term, fp32 epilogue -> g_Sf
__global__ __launch_bounds__(256, 2) void gemm3() {
    extern __shared__ __align__(128) char smem[];
    const uint32_t sb = smem_u32(smem);
    const int tid = threadIdx.x, wid = tid >> 5, lane = tid & 31;
    const int mode = (int)(blockIdx.x >> 3);
    const int n0 = (int)(blockIdx.x & 7) * 128;
    const int m0 = (int)blockIdx.y * 128;
    const int wm = (wid >> 2) * 64;
    const int wn = (wid & 3) * 32;

    float acc[4][4][4];
    if (mode == 1)
        gemm_core<false>(sb, tid, lane, wm, wn, m0, n0, g_xh, g_xl, g_wh[1], g_wl[1], acc);
    else if (mode == 0)
        gemm_core<true>(sb, tid, lane, wm, wn, m0, n0, g_xh, g_xl, g_wh[0], g_wl[0], acc);
    else
        gemm_core<true>(sb, tid, lane, wm, wn, m0, n0, g_xh, g_xl, g_wh[2], g_wl[2], acc);

#pragma unroll
    for (int i = 0; i < 4; i++) {
        const int m = m0 + wm + i * 16 + (lane >> 2);
#pragma unroll
        for (int j = 0; j < 4; j++) {
            const int n = n0 + wn + j * 8 + (lane & 3) * 2;
            const size_t o0 = (size_t)m * CD + n;
            const size_t o1 = (size_t)(m + 8) * CD + n;
            if (mode == 2) {
                *(float2*)(g_Sf + o0) = make_float2(acc[i][j][0], acc[i][j][1]);
                *(float2*)(g_Sf + o1) = make_float2(acc[i][j][2], acc[i][j][3]);
            } else if (mode == 0) {
                store_split2(g_Kh, g_Kl, o0, acc[i][j][0], acc[i][j][1]);
                store_split2(g_Kh, g_Kl, o1, acc[i][j][2], acc[i][j][3]);
            } else {
                *(__nv_bfloat162*)(g_Vb + o0) =
                    __floats2bfloat162_rn(acc[i][j][0], acc[i][j][1]);
                *(__nv_bfloat162*)(g_Vb + o1) =
                    __floats2bfloat162_rn(acc[i][j][2], acc[i][j][3]);
            }
        }
    }
}

// ---- final GEMM: (P+Sf) @ Wout^T -> out ------------------------------------
__global__ __launch_bounds__(256, 2) void gemm_out(float* __restrict__ Cout) {
    extern __shared__ __align__(128) char smem[];
    const uint32_t sb = smem_u32(smem);
    const int tid = threadIdx.x, wid = tid >> 5, lane = tid & 31;
    const int n0 = (int)blockIdx.x * 128;
    const int m0 = (int)blockIdx.y * 128;
    const int wm = (wid >> 2) * 64;
    const int wn = (wid & 3) * 32;

    float acc[4][4][4];
    gemm_core<true>(sb, tid, lane, wm, wn, m0, n0, g_xh, g_xl, g_wh[3], g_wl[3], acc);

#pragma unroll
    for (int i = 0; i < 4; i++) {
        const int m = m0 + wm + i * 16 + (lane >> 2);
#pragma unroll
        for (int j = 0; j < 4; j++) {
            const int n = n0 + wn + j * 8 + (lane & 3) * 2;
            *(float2*)(Cout + (size_t)m * CD + n) = make_float2(acc[i][j][0], acc[i][j][1]);
            *(float2*)(Cout + (size_t)(m + 8) * CD + n) = make_float2(acc[i][j][2], acc[i][j][3]);
        }
    }
}

// ============================================================================
// FA2-style causal attention on HMMA (Q == K). Epilogue fused:
// (P_norm + Sf) split -> g_xh/g_xl (A operand of gemm_out).
// ============================================================================
constexpr int A_RS = 272;
constexpr int A_TILE = 64 * A_RS;
constexpr int A_SMEM = 5 * A_TILE;

__global__ __launch_bounds__(128, 2) void fattn() {
    extern __shared__ __align__(128) char smem[];
    const uint32_t sb = smem_u32(smem);
    const uint32_t SQH = 0, SQL = A_TILE, SKH = 2 * A_TILE, SKL = 3 * A_TILE, SVB = 4 * A_TILE;

    const int qb = (int)(gridDim.x - 1 - blockIdx.x);  // heaviest first
    const int bh = blockIdx.y;
    const int b = bh >> 3, h = bh & 7;
    const int q0 = qb * 64;

    const int tid = threadIdx.x, wid = tid >> 5, lane = tid & 31;

    const __nv_bfloat16* Khg = g_Kh + (size_t)b * CS * CD + h * CHD;
    const __nv_bfloat16* Klg = g_Kl + (size_t)b * CS * CD + h * CHD;
    const __nv_bfloat16* Vbg = g_Vb + (size_t)b * CS * CD + h * CHD;

    for (int t = tid; t < 64 * 16; t += 128) {
        int row = t >> 4, g = t & 15;
        uint32_t so = (uint32_t)(row * A_RS + g * 16);
        cp16(sb + SQH + so, Khg + (size_t)(q0 + row) * CD + g * 8);
        cp16(sb + SQL + so, Klg + (size_t)(q0 + row) * CD + g * 8);
    }
    CP_COMMIT();

    float o[16][4];
#pragma unroll
    for (int t = 0; t < 16; t++)
#pragma unroll
        for (int r = 0; r < 4; r++) o[t][r] = 0.f;
    float m0r = -1e30f, m1r = -1e30f, l0 = 0.f, l1 = 0.f;
    const float scale = 0.08838834764831845f;  // 1/sqrt(128)

    for (int kb = 0; kb <= qb; kb++) {
        const int k0 = kb * 64;
        __syncthreads();
        for (int t = tid; t < 64 * 16; t += 128) {
            int row = t >> 4, g = t & 15;
            uint32_t so = (uint32_t)(row * A_RS + g * 16);
            cp16(sb + SKH + so, Khg + (size_t)(k0 + row) * CD + g * 8);
            cp16(sb + SKL + so, Klg + (size_t)(k0 + row) * CD + g * 8);
            cp16(sb + SVB + so, Vbg + (size_t)(k0 + row) * CD + g * 8);
        }
        CP_COMMIT();
        CP_WAIT0();
        __syncthreads();

        float s[8][4];
#pragma unroll
        for (int j = 0; j < 8; j++)
#pragma unroll
            for (int r = 0; r < 4; r++) s[j][r] = 0.f;

#pragma unroll
        for (int ks = 0; ks < 8; ks++) {
            uint32_t qoff = (uint32_t)((wid * 16 + (lane & 15)) * A_RS + ks * 32 +
                                       (lane >> 4) * 16);
            uint32_t qh[4], ql[4];
            ldsm4(qh, sb + SQH + qoff);
            ldsm4(ql, sb + SQL + qoff);
            uint32_t khf[16], klf[16];
#pragma unroll
            for (int j4 = 0; j4 < 4; j4++) {
                uint32_t koff = (uint32_t)((j4 * 16 + (lane & 15)) * A_RS + ks * 32 +
                                           (lane >> 4) * 16);
                ldsm4(khf + j4 * 4, sb + SKH + koff);
                ldsm4(klf + j4 * 4, sb + SKL + koff);
            }
#pragma unroll
            for (int j = 0; j < 8; j++) {
                uint32_t b2[2] = {khf[(j >> 1) * 4 + (j & 1)], khf[(j >> 1) * 4 + 2 + (j & 1)]};
                mma16816(s[j], qh, b2);
            }
#pragma unroll
            for (int j = 0; j < 8; j++) {
                uint32_t b2[2] = {klf[(j >> 1) * 4 + (j & 1)], klf[(j >> 1) * 4 + 2 + (j & 1)]};
                mma16816(s[j], qh, b2);
            }
#pragma unroll
            for (int j = 0; j < 8; j++) {
                uint32_t b2[2] = {khf[(j >> 1) * 4 + (j & 1)], khf[(j >> 1) * 4 + 2 + (j & 1)]};
                mma16816(s[j], ql, b2);
            }
        }

        const int r0l = wid * 16 + (lane >> 2);
#pragma unroll
        for (int j = 0; j < 8; j++) {
#pragma unroll
            for (int r = 0; r < 4; r++) s[j][r] = -s[j][r] * scale;
            if (kb == qb) {
                int cl = j * 8 + (lane & 3) * 2;
                if (cl > r0l) s[j][0] = -1e30f;
                if (cl + 1 > r0l) s[j][1] = -1e30f;
                if (cl > r0l + 8) s[j][2] = -1e30f;
                if (cl + 1 > r0l + 8) s[j][3] = -1e30f;
            }
        }

        float mx0 = -1e30f, mx1 = -1e30f;
#pragma unroll
        for (int j = 0; j < 8; j++) {
            mx0 = fmaxf(mx0, fmaxf(s[j][0], s[j][1]));
            mx1 = fmaxf(mx1, fmaxf(s[j][2], s[j][3]));
        }
        mx0 = fmaxf(mx0, __shfl_xor_sync(0xffffffffu, mx0, 1));
        mx0 = fmaxf(mx0, __shfl_xor_sync(0xffffffffu, mx0, 2));
        mx1 = fmaxf(mx1, __shfl_xor_sync(0xffffffffu, mx1, 1));
        mx1 = fmaxf(mx1, __shfl_xor_sync(0xffffffffu, mx1, 2));
        const float mn0 = fmaxf(m0r, mx0), mn1 = fmaxf(m1r, mx1);
        const float a0 = __expf(m0r - mn0), a1 = __expf(m1r - mn1);
        float sum0 = 0.f, sum1 = 0.f;
#pragma unroll
        for (int j = 0; j < 8; j++) {
            s[j][0] = __expf(s[j][0] - mn0);
            s[j][1] = __expf(s[j][1] - mn0);
            s[j][2] = __expf(s[j][2] - mn1);
            s[j][3] = __expf(s[j][3] - mn1);
            sum0 += s[j][0] + s[j][1];
            sum1 += s[j][2] + s[j][3];
        }
        sum0 += __shfl_xor_sync(0xffffffffu, sum0, 1);
        sum0 += __shfl_xor_sync(0xffffffffu, sum0, 2);
        sum1 += __shfl_xor_sync(0xffffffffu, sum1, 1);
        sum1 += __shfl_xor_sync(0xffffffffu, sum1, 2);
        l0 = l0 * a0 + sum0;
        l1 = l1 * a1 + sum1;
        m0r = mn0; m1r = mn1;
#pragma unroll
        for (int t = 0; t < 16; t++) {
            o[t][0] *= a0; o[t][1] *= a0; o[t][2] *= a1; o[t][3] *= a1;
        }

#pragma unroll
        for (int kg = 0; kg < 4; kg++) {
            uint32_t pa[4];
            {
                __nv_bfloat162 t0 = __floats2bfloat162_rn(s[2 * kg][0], s[2 * kg][1]);
                __nv_bfloat162 t1 = __floats2bfloat162_rn(s[2 * kg][2], s[2 * kg][3]);
                __nv_bfloat162 t2 = __floats2bfloat162_rn(s[2 * kg + 1][0], s[2 * kg + 1][1]);
                __nv_bfloat162 t3 = __floats2bfloat162_rn(s[2 * kg + 1][2], s[2 * kg + 1][3]);
                pa[0] = *(uint32_t*)&t0; pa[1] = *(uint32_t*)&t1;
                pa[2] = *(uint32_t*)&t2; pa[3] = *(uint32_t*)&t3;
            }
#pragma unroll
            for (int n2 = 0; n2 < 8; n2++) {
                uint32_t voff = (uint32_t)((kg * 16 + (lane & 15)) * A_RS + n2 * 32 +
                                           (lane >> 4) * 16);
                uint32_t vf[4];
                ldsm4t(vf, sb + SVB + voff);
                uint32_t b0[2] = {vf[0], vf[1]};
                uint32_t b1[2] = {vf[2], vf[3]};
                mma16816(o[2 * n2], pa, b0);
                mma16816(o[2 * n2 + 1], pa, b1);
            }
        }
    }

    // ---- fused epilogue: (P_norm + Sf) -> split -> g_xh/g_xl ----------------
    const float inv0 = 1.f / l0, inv1 = 1.f / l1;
    const size_t row0 = (size_t)(b * CS + q0 + wid * 16 + (lane >> 2));
#pragma unroll
    for (int t = 0; t < 16; t++) {
        const int col = h * CHD + t * 8 + (lane & 3) * 2;
        const size_t o0 = row0 * CD + col;
        const size_t o1 = (row0 + 8) * CD + col;
        float2 sf0 = *(const float2*)(g_Sf + o0);
        float2 sf1 = *(const float2*)(g_Sf + o1);
        store_split2(g_xh, g_xl, o0, o[t][0] * inv0 + sf0.x, o[t][1] * inv0 + sf0.y);
        store_split2(g_xh, g_xl, o1, o[t][2] * inv1 + sf1.x, o[t][3] * inv1 + sf1.y);
    }
}

// ============================================================================
// launch
// ============================================================================
extern "C" void kernel_launch(void* const* d_in, const int* in_sizes, int n_in,
                              void* d_out, int out_size) {
    const float* x  = (const float*)d_in[0];
    const float* Wk = (const float*)d_in[1];
    const float* Wv = (const float*)d_in[2];
    const float* Ws = (const float*)d_in[3];
    const float* Wo = (const float*)d_in[4];
    float* out = (float*)d_out;

    cudaFuncSetAttribute(gemm3, cudaFuncAttributeMaxDynamicSharedMemorySize, G_SMEM);
    cudaFuncSetAttribute(gemm_out, cudaFuncAttributeMaxDynamicSharedMemorySize, G_SMEM);
    cudaFuncSetAttribute(fattn, cudaFuncAttributeMaxDynamicSharedMemorySize, A_SMEM);

    const int PB = (int)((XQ + 4 * WQ) / 256);
    prep<<<PB, 256>>>(x, Wk, Wv, Ws, Wo);

    gemm3<<<dim3(24, CM / 128), 256, G_SMEM>>>();     // -> g_Kh/g_Kl, g_Vb, g_Sf

    fattn<<<dim3(CS / 64, CB * CH), 128, A_SMEM>>>(); // -> g_xh/g_xl (=P+Sf split)

    gemm_out<<<dim3(CD / 128, CM / 128), 256, G_SMEM>>>(out);
}

// round 9
// speedup vs baseline: 1.1246x; 1.0183x over previous
#include <cuda_runtime.h>
#include <cuda_bf16.h>
#include <cstdint>
#include <math.h>

// ---------------- problem constants ----------------
constexpr int CB = 2;        // batch
constexpr int CS = 2048;     // seq
constexpr int CD = 1024;     // model dim
constexpr int CH = 8;        // heads
constexpr int CHD = 128;     // head dim
constexpr int CM = CB * CS;  // 4096 rows

// ---------------- scratch (device globals; no allocations allowed) ----------
__device__ float g_Sf[CB * CS * CD];  // self_force = x @ Wself^T (fp32)

__device__ __nv_bfloat16 g_xh[CM * CD];
__device__ __nv_bfloat16 g_xl[CM * CD];
__device__ __nv_bfloat16 g_wh[4][CD * CD];
__device__ __nv_bfloat16 g_wl[4][CD * CD];

__device__ __nv_bfloat16 g_Kh[CB * CS * CD];
__device__ __nv_bfloat16 g_Kl[CB * CS * CD];
__device__ __nv_bfloat16 g_Vb[CB * CS * CD];

// ============================================================================
// PTX helpers (family-common sm_80+ only; tcgen05 unavailable on this ptxas)
// ============================================================================
__device__ __forceinline__ uint32_t smem_u32(const void* p) {
    uint32_t a;
    asm("{ .reg .u64 t; cvta.to.shared.u64 t, %1; cvt.u32.u64 %0, t; }" : "=r"(a) : "l"(p));
    return a;
}
__device__ __forceinline__ void cp16(uint32_t dst, const void* src) {
    asm volatile("cp.async.cg.shared.global [%0], [%1], 16;" :: "r"(dst), "l"(src) : "memory");
}
#define CP_COMMIT() asm volatile("cp.async.commit_group;" ::: "memory")
#define CP_WAIT0()  asm volatile("cp.async.wait_group 0;" ::: "memory")

__device__ __forceinline__ void ldsm4(uint32_t* r, uint32_t addr) {
    asm volatile("ldmatrix.sync.aligned.m8n8.x4.shared.b16 {%0,%1,%2,%3}, [%4];"
                 : "=r"(r[0]), "=r"(r[1]), "=r"(r[2]), "=r"(r[3]) : "r"(addr));
}
__device__ __forceinline__ void ldsm4t(uint32_t* r, uint32_t addr) {
    asm volatile("ldmatrix.sync.aligned.m8n8.x4.trans.shared.b16 {%0,%1,%2,%3}, [%4];"
                 : "=r"(r[0]), "=r"(r[1]), "=r"(r[2]), "=r"(r[3]) : "r"(addr));
}
__device__ __forceinline__ void mma16816(float* d, const uint32_t* a, const uint32_t* b) {
    asm volatile(
        "mma.sync.aligned.m16n8k16.row.col.f32.bf16.bf16.f32 "
        "{%0,%1,%2,%3}, {%4,%5,%6,%7}, {%8,%9}, {%0,%1,%2,%3};\n"
        : "+f"(d[0]), "+f"(d[1]), "+f"(d[2]), "+f"(d[3])
        : "r"(a[0]), "r"(a[1]), "r"(a[2]), "r"(a[3]), "r"(b[0]), "r"(b[1]));
}

// ---- fp32 -> bf16 hi/lo helpers --------------------------------------------
__device__ __forceinline__ void split4(float4 v, __nv_bfloat162* hi2, __nv_bfloat162* lo2,
                                       size_t i2) {
    __nv_bfloat16 h0 = __float2bfloat16_rn(v.x), h1 = __float2bfloat16_rn(v.y);
    __nv_bfloat16 h2 = __float2bfloat16_rn(v.z), h3 = __float2bfloat16_rn(v.w);
    __nv_bfloat16 l0 = __float2bfloat16_rn(v.x - __bfloat162float(h0));
    __nv_bfloat16 l1 = __float2bfloat16_rn(v.y - __bfloat162float(h1));
    __nv_bfloat16 l2 = __float2bfloat16_rn(v.z - __bfloat162float(h2));
    __nv_bfloat16 l3 = __float2bfloat16_rn(v.w - __bfloat162float(h3));
    hi2[i2]     = __nv_bfloat162(h0, h1);
    hi2[i2 + 1] = __nv_bfloat162(h2, h3);
    lo2[i2]     = __nv_bfloat162(l0, l1);
    lo2[i2 + 1] = __nv_bfloat162(l2, l3);
}
__device__ __forceinline__ void store_split2(__nv_bfloat16* H, __nv_bfloat16* L,
                                             size_t off, float a, float b) {
    __nv_bfloat16 h0 = __float2bfloat16_rn(a), h1 = __float2bfloat16_rn(b);
    __nv_bfloat16 l0 = __float2bfloat16_rn(a - __bfloat162float(h0));
    __nv_bfloat16 l1 = __float2bfloat16_rn(b - __bfloat162float(h1));
    *(__nv_bfloat162*)(H + off) = __nv_bfloat162(h0, h1);
    *(__nv_bfloat162*)(L + off) = __nv_bfloat162(l0, l1);
}

// ============================================================================
// prep: one kernel splitting x and all 4 weights into bf16 hi/lo
// ============================================================================
constexpr size_t XQ = (size_t)CM * CD / 4;
constexpr size_t WQ = (size_t)CD * CD / 4;
__global__ __launch_bounds__(256) void prep(const float* __restrict__ x,
                                            const float* __restrict__ Wk,
                                            const float* __restrict__ Wv,
                                            const float* __restrict__ Ws,
                                            const float* __restrict__ Wo) {
    size_t i = (size_t)blockIdx.x * 256 + threadIdx.x;
    if (i < XQ) {
        split4(((const float4*)x)[i], (__nv_bfloat162*)g_xh, (__nv_bfloat162*)g_xl, i * 2);
    } else {
        size_t j = i - XQ;
        int w = (int)(j / WQ);
        size_t o = j % WQ;
        const float* W = (w == 0) ? Wk : (w == 1) ? Wv : (w == 2) ? Ws : Wo;
        split4(((const float4*)W)[o], (__nv_bfloat162*)g_wh[w], (__nv_bfloat162*)g_wl[w], o * 2);
    }
}

// ============================================================================
// HMMA bf16-split GEMM core:  C = A @ W^T, 128x128 CTA tile, 4 warps of 64x64.
// Wide warp tile cuts smem crossbar traffic to 85 B per mma (was 128).
// F3=true : 3-term split (Ah*Bh + Ah*Bl + Al*Bh).  F3=false : plain bf16.
// ============================================================================
constexpr int RSTRIDE = 80;
constexpr int TILE_B = 128 * RSTRIDE;
constexpr int STAGE_B = 4 * TILE_B;
constexpr int G_SMEM = 2 * STAGE_B;

template <bool F3>
__device__ __forceinline__ void g_load(uint32_t st_, int m0, int n0, int k0, int tid,
                                       const __nv_bfloat16* Ah_, const __nv_bfloat16* Al_,
                                       const __nv_bfloat16* Bh_, const __nv_bfloat16* Bl_) {
    const int lr = tid >> 2;      // 0..31
    const int lc = tid & 3;       // 0..3 (16B segment)
#pragma unroll
    for (int rr = 0; rr < 4; rr++) {
        const int row = lr + rr * 32;
        const uint32_t so = (uint32_t)(row * RSTRIDE + lc * 16);
        const size_t gA = (size_t)(m0 + row) * CD + k0 + lc * 8;
        const size_t gB = (size_t)(n0 + row) * CD + k0 + lc * 8;
        cp16(st_ + 0 * TILE_B + so, Ah_ + gA);
        cp16(st_ + 2 * TILE_B + so, Bh_ + gB);
        if (F3) {
            cp16(st_ + 1 * TILE_B + so, Al_ + gA);
            cp16(st_ + 3 * TILE_B + so, Bl_ + gB);
        }
    }
    CP_COMMIT();
}

template <bool F3>
__device__ __forceinline__ void gemm_core(uint32_t sb, int tid, int lane, int wm, int wn,
                                          int m0, int n0,
                                          const __nv_bfloat16* Ah_, const __nv_bfloat16* Al_,
                                          const __nv_bfloat16* Bh_, const __nv_bfloat16* Bl_,
                                          float acc[4][8][4]) {
#pragma unroll
    for (int i = 0; i < 4; i++)
#pragma unroll
        for (int j = 0; j < 8; j++)
#pragma unroll
            for (int r = 0; r < 4; r++) acc[i][j][r] = 0.f;

    g_load<F3>(sb, m0, n0, 0, tid, Ah_, Al_, Bh_, Bl_);

    constexpr int NC = CD / 32;
    for (int c = 0; c < NC; c++) {
        CP_WAIT0();
        __syncthreads();
        if (c + 1 < NC)
            g_load<F3>(sb + ((c + 1) & 1) * STAGE_B, m0, n0, (c + 1) * 32, tid,
                       Ah_, Al_, Bh_, Bl_);

        const uint32_t st = sb + (c & 1) * STAGE_B;
#pragma unroll
        for (int h = 0; h < 2; h++) {
            uint32_t bh[16], bl[16];
#pragma unroll
            for (int j4 = 0; j4 < 4; j4++) {
                uint32_t off = (uint32_t)((wn + j4 * 16 + (lane & 15)) * RSTRIDE +
                                          (h * 2 + (lane >> 4)) * 16);
                ldsm4(bh + j4 * 4, st + 2 * TILE_B + off);
                if (F3) ldsm4(bl + j4 * 4, st + 3 * TILE_B + off);
            }
#pragma unroll
            for (int i = 0; i < 4; i++) {
                uint32_t aoff = (uint32_t)((wm + i * 16 + (lane & 15)) * RSTRIDE +
                                           (h * 2 + (lane >> 4)) * 16);
                uint32_t ah[4], al[4];
                ldsm4(ah, st + 0 * TILE_B + aoff);
                if (F3) ldsm4(al, st + 1 * TILE_B + aoff);
#pragma unroll
                for (int j = 0; j < 8; j++) {
                    uint32_t b2[2] = {bh[(j >> 1) * 4 + (j & 1)], bh[(j >> 1) * 4 + 2 + (j & 1)]};
                    mma16816(acc[i][j], ah, b2);
                }
                if (F3) {
#pragma unroll
                    for (int j = 0; j < 8; j++) {
                        uint32_t b2[2] = {bl[(j >> 1) * 4 + (j & 1)],
                                          bl[(j >> 1) * 4 + 2 + (j & 1)]};
                        mma16816(acc[i][j], ah, b2);
                    }
#pragma unroll
                    for (int j = 0; j < 8; j++) {
                        uint32_t b2[2] = {bh[(j >> 1) * 4 + (j & 1)],
                                          bh[(j >> 1) * 4 + 2 + (j & 1)]};
                        mma16816(acc[i][j], al, b2);
                    }
                }
            }
        }
        __syncthreads();  // all warps done with buffer (c&1) before it is reloaded
    }
}

// ---- the 3 projection GEMMs in one launch ----------------------------------
__global__ __launch_bounds__(128, 2) void gemm3() {
    extern __shared__ __align__(128) char smem[];
    const uint32_t sb = smem_u32(smem);
    const int tid = threadIdx.x, wid = tid >> 5, lane = tid & 31;
    const int mode = (int)(blockIdx.x >> 3);
    const int n0 = (int)(blockIdx.x & 7) * 128;
    const int m0 = (int)blockIdx.y * 128;
    const int wm = (wid >> 1) * 64;
    const int wn = (wid & 1) * 64;

    float acc[4][8][4];
    if (mode == 1)
        gemm_core<false>(sb, tid, lane, wm, wn, m0, n0, g_xh, g_xl, g_wh[1], g_wl[1], acc);
    else if (mode == 0)
        gemm_core<true>(sb, tid, lane, wm, wn, m0, n0, g_xh, g_xl, g_wh[0], g_wl[0], acc);
    else
        gemm_core<true>(sb, tid, lane, wm, wn, m0, n0, g_xh, g_xl, g_wh[2], g_wl[2], acc);

#pragma unroll
    for (int i = 0; i < 4; i++) {
        const int m = m0 + wm + i * 16 + (lane >> 2);
#pragma unroll
        for (int j = 0; j < 8; j++) {
            const int n = n0 + wn + j * 8 + (lane & 3) * 2;
            const size_t o0 = (size_t)m * CD + n;
            const size_t o1 = (size_t)(m + 8) * CD + n;
            if (mode == 2) {
                *(float2*)(g_Sf + o0) = make_float2(acc[i][j][0], acc[i][j][1]);
                *(float2*)(g_Sf + o1) = make_float2(acc[i][j][2], acc[i][j][3]);
            } else if (mode == 0) {
                store_split2(g_Kh, g_Kl, o0, acc[i][j][0], acc[i][j][1]);
                store_split2(g_Kh, g_Kl, o1, acc[i][j][2], acc[i][j][3]);
            } else {
                *(__nv_bfloat162*)(g_Vb + o0) =
                    __floats2bfloat162_rn(acc[i][j][0], acc[i][j][1]);
                *(__nv_bfloat162*)(g_Vb + o1) =
                    __floats2bfloat162_rn(acc[i][j][2], acc[i][j][3]);
            }
        }
    }
}

// ---- final GEMM: (P+Sf) @ Wout^T -> out ------------------------------------
__global__ __launch_bounds__(128, 2) void gemm_out(float* __restrict__ Cout) {
    extern __shared__ __align__(128) char smem[];
    const uint32_t sb = smem_u32(smem);
    const int tid = threadIdx.x, wid = tid >> 5, lane = tid & 31;
    const int n0 = (int)blockIdx.x * 128;
    const int m0 = (int)blockIdx.y * 128;
    const int wm = (wid >> 1) * 64;
    const int wn = (wid & 1) * 64;

    float acc[4][8][4];
    gemm_core<true>(sb, tid, lane, wm, wn, m0, n0, g_xh, g_xl, g_wh[3], g_wl[3], acc);

#pragma unroll
    for (int i = 0; i < 4; i++) {
        const int m = m0 + wm + i * 16 + (lane >> 2);
#pragma unroll
        for (int j = 0; j < 8; j++) {
            const int n = n0 + wn + j * 8 + (lane & 3) * 2;
            *(float2*)(Cout + (size_t)m * CD + n) = make_float2(acc[i][j][0], acc[i][j][1]);
            *(float2*)(Cout + (size_t)(m + 8) * CD + n) = make_float2(acc[i][j][2], acc[i][j][3]);
        }
    }
}

// ============================================================================
// FA2-style causal attention on HMMA (Q == K). Q fragments hoisted to
// registers before the key loop (Q is loop-invariant: saves 14% smem traffic).
// Epilogue fused: (P_norm + Sf) split -> g_xh/g_xl.
// ============================================================================
constexpr int A_RS = 272;
constexpr int A_TILE = 64 * A_RS;
constexpr int A_SMEM = 5 * A_TILE;

__global__ __launch_bounds__(128, 2) void fattn() {
    extern __shared__ __align__(128) char smem[];
    const uint32_t sb = smem_u32(smem);
    const uint32_t SQH = 0, SQL = A_TILE, SKH = 2 * A_TILE, SKL = 3 * A_TILE, SVB = 4 * A_TILE;

    const int qb = (int)(gridDim.x - 1 - blockIdx.x);  // heaviest first
    const int bh = blockIdx.y;
    const int b = bh >> 3, h = bh & 7;
    const int q0 = qb * 64;

    const int tid = threadIdx.x, wid = tid >> 5, lane = tid & 31;

    const __nv_bfloat16* Khg = g_Kh + (size_t)b * CS * CD + h * CHD;
    const __nv_bfloat16* Klg = g_Kl + (size_t)b * CS * CD + h * CHD;
    const __nv_bfloat16* Vbg = g_Vb + (size_t)b * CS * CD + h * CHD;

    for (int t = tid; t < 64 * 16; t += 128) {
        int row = t >> 4, g = t & 15;
        uint32_t so = (uint32_t)(row * A_RS + g * 16);
        cp16(sb + SQH + so, Khg + (size_t)(q0 + row) * CD + g * 8);
        cp16(sb + SQL + so, Klg + (size_t)(q0 + row) * CD + g * 8);
    }
    CP_COMMIT();
    CP_WAIT0();
    __syncthreads();

    // hoist Q fragments (hi/lo) for all 8 k16 steps into registers
    uint32_t qhr[8][4], qlr[8][4];
#pragma unroll
    for (int ks = 0; ks < 8; ks++) {
        uint32_t qoff = (uint32_t)((wid * 16 + (lane & 15)) * A_RS + ks * 32 +
                                   (lane >> 4) * 16);
        ldsm4(qhr[ks], sb + SQH + qoff);
        ldsm4(qlr[ks], sb + SQL + qoff);
    }

    float o[16][4];
#pragma unroll
    for (int t = 0; t < 16; t++)
#pragma unroll
        for (int r = 0; r < 4; r++) o[t][r] = 0.f;
    float m0r = -1e30f, m1r = -1e30f, l0 = 0.f, l1 = 0.f;
    const float scale = 0.08838834764831845f;  // 1/sqrt(128)

    for (int kb = 0; kb <= qb; kb++) {
        const int k0 = kb * 64;
        __syncthreads();
        for (int t = tid; t < 64 * 16; t += 128) {
            int row = t >> 4, g = t & 15;
            uint32_t so = (uint32_t)(row * A_RS + g * 16);
            cp16(sb + SKH + so, Khg + (size_t)(k0 + row) * CD + g * 8);
            cp16(sb + SKL + so, Klg + (size_t)(k0 + row) * CD + g * 8);
            cp16(sb + SVB + so, Vbg + (size_t)(k0 + row) * CD + g * 8);
        }
        CP_COMMIT();
        CP_WAIT0();
        __syncthreads();

        float s[8][4];
#pragma unroll
        for (int j = 0; j < 8; j++)
#pragma unroll
            for (int r = 0; r < 4; r++) s[j][r] = 0.f;

#pragma unroll
        for (int ks = 0; ks < 8; ks++) {
            uint32_t khf[16], klf[16];
#pragma unroll
            for (int j4 = 0; j4 < 4; j4++) {
                uint32_t koff = (uint32_t)((j4 * 16 + (lane & 15)) * A_RS + ks * 32 +
                                           (lane >> 4) * 16);
                ldsm4(khf + j4 * 4, sb + SKH + koff);
                ldsm4(klf + j4 * 4, sb + SKL + koff);
            }
#pragma unroll
            for (int j = 0; j < 8; j++) {
                uint32_t b2[2] = {khf[(j >> 1) * 4 + (j & 1)], khf[(j >> 1) * 4 + 2 + (j & 1)]};
                mma16816(s[j], qhr[ks], b2);
            }
#pragma unroll
            for (int j = 0; j < 8; j++) {
                uint32_t b2[2] = {klf[(j >> 1) * 4 + (j & 1)], klf[(j >> 1) * 4 + 2 + (j & 1)]};
                mma16816(s[j], qhr[ks], b2);
            }
#pragma unroll
            for (int j = 0; j < 8; j++) {
                uint32_t b2[2] = {khf[(j >> 1) * 4 + (j & 1)], khf[(j >> 1) * 4 + 2 + (j & 1)]};
                mma16816(s[j], qlr[ks], b2);
            }
        }

        const int r0l = wid * 16 + (lane >> 2);
#pragma unroll
        for (int j = 0; j < 8; j++) {
#pragma unroll
            for (int r = 0; r < 4; r++) s[j][r] = -s[j][r] * scale;
            if (kb == qb) {
                int cl = j * 8 + (lane & 3) * 2;
                if (cl > r0l) s[j][0] = -1e30f;
                if (cl + 1 > r0l) s[j][1] = -1e30f;
                if (cl > r0l + 8) s[j][2] = -1e30f;
                if (cl + 1 > r0l + 8) s[j][3] = -1e30f;
            }
        }

        float mx0 = -1e30f, mx1 = -1e30f;
#pragma unroll
        for (int j = 0; j < 8; j++) {
            mx0 = fmaxf(mx0, fmaxf(s[j][0], s[j][1]));
            mx1 = fmaxf(mx1, fmaxf(s[j][2], s[j][3]));
        }
        mx0 = fmaxf(mx0, __shfl_xor_sync(0xffffffffu, mx0, 1));
        mx0 = fmaxf(mx0, __shfl_xor_sync(0xffffffffu, mx0, 2));
        mx1 = fmaxf(mx1, __shfl_xor_sync(0xffffffffu, mx1, 1));
        mx1 = fmaxf(mx1, __shfl_xor_sync(0xffffffffu, mx1, 2));
        const float mn0 = fmaxf(m0r, mx0), mn1 = fmaxf(m1r, mx1);
        const float a0 = __expf(m0r - mn0), a1 = __expf(m1r - mn1);
        float sum0 = 0.f, sum1 = 0.f;
#pragma unroll
        for (int j = 0; j < 8; j++) {
            s[j][0] = __expf(s[j][0] - mn0);
            s[j][1] = __expf(s[j][1] - mn0);
            s[j][2] = __expf(s[j][2] - mn1);
            s[j][3] = __expf(s[j][3] - mn1);
            sum0 += s[j][0] + s[j][1];
            sum1 += s[j][2] + s[j][3];
        }
        sum0 += __shfl_xor_sync(0xffffffffu, sum0, 1);
        sum0 += __shfl_xor_sync(0xffffffffu, sum0, 2);
        sum1 += __shfl_xor_sync(0xffffffffu, sum1, 1);
        sum1 += __shfl_xor_sync(0xffffffffu, sum1, 2);
        l0 = l0 * a0 + sum0;
        l1 = l1 * a1 + sum1;
        m0r = mn0; m1r = mn1;
#pragma unroll
        for (int t = 0; t < 16; t++) {
            o[t][0] *= a0; o[t][1] *= a0; o[t][2] *= a1; o[t][3] *= a1;
        }

#pragma unroll
        for (int kg = 0; kg < 4; kg++) {
            uint32_t pa[4];
            {
                __nv_bfloat162 t0 = __floats2bfloat162_rn(s[2 * kg][0], s[2 * kg][1]);
                __nv_bfloat162 t1 = __floats2bfloat162_rn(s[2 * kg][2], s[2 * kg][3]);
                __nv_bfloat162 t2 = __floats2bfloat162_rn(s[2 * kg + 1][0], s[2 * kg + 1][1]);
                __nv_bfloat162 t3 = __floats2bfloat162_rn(s[2 * kg + 1][2], s[2 * kg + 1][3]);
                pa[0] = *(uint32_t*)&t0; pa[1] = *(uint32_t*)&t1;
                pa[2] = *(uint32_t*)&t2; pa[3] = *(uint32_t*)&t3;
            }
#pragma unroll
            for (int n2 = 0; n2 < 8; n2++) {
                uint32_t voff = (uint32_t)((kg * 16 + (lane & 15)) * A_RS + n2 * 32 +
                                           (lane >> 4) * 16);
                uint32_t vf[4];
                ldsm4t(vf, sb + SVB + voff);
                uint32_t b0[2] = {vf[0], vf[1]};
                uint32_t b1[2] = {vf[2], vf[3]};
                mma16816(o[2 * n2], pa, b0);
                mma16816(o[2 * n2 + 1], pa, b1);
            }
        }
    }

    // ---- fused epilogue: (P_norm + Sf) -> split -> g_xh/g_xl ----------------
    const float inv0 = 1.f / l0, inv1 = 1.f / l1;
    const size_t row0 = (size_t)(b * CS + q0 + wid * 16 + (lane >> 2));
#pragma unroll
    for (int t = 0; t < 16; t++) {
        const int col = h * CHD + t * 8 + (lane & 3) * 2;
        const size_t o0 = row0 * CD + col;
        const size_t o1 = (row0 + 8) * CD + col;
        float2 sf0 = *(const float2*)(g_Sf + o0);
        float2 sf1 = *(const float2*)(g_Sf + o1);
        store_split2(g_xh, g_xl, o0, o[t][0] * inv0 + sf0.x, o[t][1] * inv0 + sf0.y);
        store_split2(g_xh, g_xl, o1, o[t][2] * inv1 + sf1.x, o[t][3] * inv1 + sf1.y);
    }
}

// ============================================================================
// launch
// ============================================================================
extern "C" void kernel_launch(void* const* d_in, const int* in_sizes, int n_in,
                              void* d_out, int out_size) {
    const float* x  = (const float*)d_in[0];
    const float* Wk = (const float*)d_in[1];
    const float* Wv = (const float*)d_in[2];
    const float* Ws = (const float*)d_in[3];
    const float* Wo = (const float*)d_in[4];
    float* out = (float*)d_out;

    cudaFuncSetAttribute(gemm3, cudaFuncAttributeMaxDynamicSharedMemorySize, G_SMEM);
    cudaFuncSetAttribute(gemm_out, cudaFuncAttributeMaxDynamicSharedMemorySize, G_SMEM);
    cudaFuncSetAttribute(fattn, cudaFuncAttributeMaxDynamicSharedMemorySize, A_SMEM);

    const int PB = (int)((XQ + 4 * WQ) / 256);
    prep<<<PB, 256>>>(x, Wk, Wv, Ws, Wo);

    gemm3<<<dim3(24, CM / 128), 128, G_SMEM>>>();     // -> g_Kh/g_Kl, g_Vb, g_Sf

    fattn<<<dim3(CS / 64, CB * CH), 128, A_SMEM>>>(); // -> g_xh/g_xl (=P+Sf split)

    gemm_out<<<dim3(CD / 128, CM / 128), 128, G_SMEM>>>(out);
}